// round 3
// baseline (speedup 1.0000x reference)
#include <cuda_runtime.h>
#include <cuda_bf16.h>

#define T_STEPS 10
#define NN      50000
#define F_INN   2
#define F_OUTN  16
#define HID     32
#define NE      800000

#define BN      128     // nodes per block in main kernel
#define NTHR    256

typedef unsigned long long ull;

// ---------------- device scratch (no allocations allowed) ----------------
__device__ float g_deg [NN];
__device__ float g_dinv[NN];
__device__ float g_xs  [NN * 20];   // dinv[n] * x, laid out [n][t*2+k]
__device__ float g_acc [NN * 20];   // aggregated (seeded with self-loop term)

// ---------------- small prep kernels ----------------
__global__ void k_init_deg() {
    int n = blockIdx.x * blockDim.x + threadIdx.x;
    if (n < NN) g_deg[n] = 1.0f;          // self-loop
}

__global__ void k_count(const int* __restrict__ ei) {
    int e = blockIdx.x * blockDim.x + threadIdx.x;
    if (e < NE) atomicAdd(&g_deg[ei[NE + e]], 1.0f);
}

__global__ void k_dinv() {
    int n = blockIdx.x * blockDim.x + threadIdx.x;
    if (n < NN) g_dinv[n] = rsqrtf(g_deg[n]);   // deg >= 1 always
}

// xs[n][t*2+k] = dinv[n] * x[t][n][k]; acc seeded identically (self-loop msg)
__global__ void k_xs(const float* __restrict__ x) {
    int idx = blockIdx.x * blockDim.x + threadIdx.x;   // over T*N*2 = 1M
    if (idx < T_STEPS * NN * F_INN) {
        int k = idx & 1;
        int n = (idx >> 1) % NN;
        int t = idx / (NN * F_INN);
        float v = g_dinv[n] * x[idx];
        int o = n * 20 + t * 2 + k;
        g_xs[o]  = v;
        g_acc[o] = v;
    }
}

// push-scatter: acc[dst] += xs[src], 20 floats per edge, 5 float4-chunks
__global__ void k_scatter(const int* __restrict__ ei) {
    int idx = blockIdx.x * blockDim.x + threadIdx.x;
    if (idx >= NE * 5) return;
    int e = idx / 5;
    int q = idx - e * 5;
    int s = ei[e];
    int d = ei[NE + e];
    float4 v = *(const float4*)&g_xs[s * 20 + q * 4];
    float* a = &g_acc[d * 20 + q * 4];
    atomicAdd(a + 0, v.x);
    atomicAdd(a + 1, v.y);
    atomicAdd(a + 2, v.z);
    atomicAdd(a + 3, v.w);
}

// ---------------- math helpers ----------------
__device__ __forceinline__ float tanhap(float x) {
    float y;
    asm("tanh.approx.f32 %0, %1;" : "=f"(y) : "f"(x));
    return y;
}
__device__ __forceinline__ float sigf(float x) {
    return fmaf(tanhap(0.5f * x), 0.5f, 0.5f);
}

__device__ __forceinline__ void fma2(ull& a, ull x, ull w) {
    asm("fma.rn.f32x2 %0, %1, %2, %0;" : "+l"(a) : "l"(x), "l"(w));
}
__device__ __forceinline__ void unpack2(float& lo, float& hi, ull v) {
    asm("mov.b64 {%0, %1}, %2;" : "=f"(lo), "=f"(hi) : "l"(v));
}

// one k-step: 4 LDS.128 (2 dup-weight, 2 activation), 32 FFMA2 (=64 FMA lanes)
// wsrow: duplicated weights, 256 floats/row; vrow: activations, 128 floats/row
__device__ __forceinline__ void gemm_step2(const float* __restrict__ wsrow,
                                           const float* __restrict__ vrow,
                                           int ubase2, int nbase,
                                           ull acc[8][4]) {
    ulonglong2 wq0 = *(const ulonglong2*)(wsrow + ubase2);       // c+0,c+1 (dup)
    ulonglong2 wq1 = *(const ulonglong2*)(wsrow + ubase2 + 4);   // c+2,c+3
    ulonglong2 wq2 = *(const ulonglong2*)(wsrow + ubase2 + 8);   // c+4,c+5
    ulonglong2 wq3 = *(const ulonglong2*)(wsrow + ubase2 + 12);  // c+6,c+7
    ulonglong2 xq0 = *(const ulonglong2*)(vrow + nbase);         // node pairs 0,1
    ulonglong2 xq1 = *(const ulonglong2*)(vrow + nbase + 4);     // node pairs 2,3
    ull w[8] = {wq0.x, wq0.y, wq1.x, wq1.y, wq2.x, wq2.y, wq3.x, wq3.y};
    ull xp[4] = {xq0.x, xq0.y, xq1.x, xq1.y};
#pragma unroll
    for (int c = 0; c < 8; c++)
#pragma unroll
        for (int p = 0; p < 4; p++)
            fma2(acc[c][p], xp[p], w[c]);
}

// unpack gate accumulators, apply LSTM cell for 2 units x 8 nodes
__device__ __forceinline__ void lstm_act2(ull acc[8][4],
                                          const float* __restrict__ bias,
                                          int ucol, float cA[8], float cB[8],
                                          float hA[8], float hB[8]) {
    float gA[4][8], gB[4][8];
#pragma unroll
    for (int c = 0; c < 4; c++)
#pragma unroll
        for (int p = 0; p < 4; p++) {
            unpack2(gA[c][2 * p], gA[c][2 * p + 1], acc[c][p]);
            unpack2(gB[c][2 * p], gB[c][2 * p + 1], acc[c + 4][p]);
        }
    float biA = bias[ucol + 0], bfA = bias[ucol + 1];
    float bgA = bias[ucol + 2], boA = bias[ucol + 3];
    float biB = bias[ucol + 4], bfB = bias[ucol + 5];
    float bgB = bias[ucol + 6], boB = bias[ucol + 7];
#pragma unroll
    for (int j = 0; j < 8; j++) {
        float iv = sigf(gA[0][j] + biA);
        float fv = sigf(gA[1][j] + bfA);
        float gv = tanhap(gA[2][j] + bgA);
        float ov = sigf(gA[3][j] + boA);
        cA[j] = fv * cA[j] + iv * gv;
        hA[j] = ov * tanhap(cA[j]);
        iv = sigf(gB[0][j] + biB);
        fv = sigf(gB[1][j] + bfB);
        gv = tanhap(gB[2][j] + bgB);
        ov = sigf(gB[3][j] + boB);
        cB[j] = fv * cB[j] + iv * gv;
        hB[j] = ov * tanhap(cB[j]);
    }
}

// smem layout (in floats)
#define O_WSD0  0                        // [48][256] duplicated
#define O_WSD1  (O_WSD0 + 48 * 256)      // 12288, [64][256]
#define O_B0    (O_WSD1 + 64 * 256)      // 28672, [128]
#define O_B1    (O_B0 + 128)             // 28800
#define O_OW    (O_B1 + 128)             // 28928, [32]
#define O_GW    (O_OW + 32)              // 28960, [32]
#define O_GB    (O_GW + 32)              // 28992, [16]
#define O_XA    (O_GB + 16)              // 29008, [10][2][128]
#define O_INT   (O_XA + T_STEPS * 2 * 128)   // 31568, [16][128]
#define O_H0    (O_INT + 16 * 128)       // 33616, [32][128]
#define O_H1    (O_H0 + 32 * 128)        // 37712, [32][128]
#define SM_FLOATS (O_H1 + 32 * 128)      // 41808
#define SM_BYTES  (SM_FLOATS * 4)        // 167232

__global__ __launch_bounds__(NTHR, 1)
void k_main(const float* __restrict__ wih0, const float* __restrict__ whh0,
            const float* __restrict__ bih0, const float* __restrict__ bhh0,
            const float* __restrict__ wih1, const float* __restrict__ whh1,
            const float* __restrict__ bih1, const float* __restrict__ bhh1,
            const float* __restrict__ gw,   const float* __restrict__ gb,
            const float* __restrict__ ow,   const float* __restrict__ ob,
            float* __restrict__ out) {
    extern __shared__ float sm[];
    float* wsd0  = sm + O_WSD0;
    float* wsd1  = sm + O_WSD1;
    float* bias0 = sm + O_B0;
    float* bias1 = sm + O_B1;
    float* outw  = sm + O_OW;
    float* gws   = sm + O_GW;
    float* gbs   = sm + O_GB;
    float* xa    = sm + O_XA;
    float* intb  = sm + O_INT;
    float* h0b   = sm + O_H0;
    float* h1b   = sm + O_H1;

    int tid   = threadIdx.x;
    int node0 = blockIdx.x * BN;

    // ---- prologue: weights duplicated into [k][(unit*4+gatetype)*2 + dup] ----
    for (int idx = tid; idx < 48 * 256; idx += NTHR) {
        int k = idx >> 8, cc = idx & 255;
        int c = cc >> 1;
        int u = c >> 2, ty = c & 3;
        int row = ty * 32 + u;                      // torch gate order i,f,g,o
        wsd0[idx] = (k < 16) ? wih0[row * 16 + k] : whh0[row * 32 + (k - 16)];
    }
    for (int idx = tid; idx < 64 * 256; idx += NTHR) {
        int k = idx >> 8, cc = idx & 255;
        int c = cc >> 1;
        int u = c >> 2, ty = c & 3;
        int row = ty * 32 + u;
        wsd1[idx] = (k < 32) ? wih1[row * 32 + k] : whh1[row * 32 + (k - 32)];
    }
    if (tid < 128) {
        int u = tid >> 2, ty = tid & 3;
        int row = ty * 32 + u;
        bias0[tid] = bih0[row] + bhh0[row];
        bias1[tid] = bih1[row] + bhh1[row];
    }
    if (tid < 32) { outw[tid] = ow[tid]; gws[tid] = gw[tid]; }
    if (tid < 16) gbs[tid] = gb[tid];
    for (int idx = tid; idx < 32 * 128; idx += NTHR) { h0b[idx] = 0.0f; h1b[idx] = 0.0f; }

    // ---- raw aggregated features for this tile: xa[t][k][nl] = dinv*acc ----
    for (int idx = tid; idx < T_STEPS * 2 * BN; idx += NTHR) {
        int nl = idx & (BN - 1);
        int rest = idx >> 7;            // t*2 + k
        int n = node0 + nl;
        if (n >= NN) n = NN - 1;        // clamp (tail block)
        xa[idx] = g_acc[n * 20 + rest] * g_dinv[n];
    }
    __syncthreads();

    // ---- main time loop ----
    int up = tid >> 4;          // 0..15 unit-pair
    int ng = tid & 15;          // 0..15 node-group (8 nodes)
    int ubase2 = up * 16;       // offset into duplicated ws rows
    int ucol   = up * 8;        // offset into bias layout
    int nbase  = ng * 8;

    float c0a[8] = {}, c0b[8] = {};   // cell state layer0, units up*2 / up*2+1
    float c1a[8] = {}, c1b[8] = {};   // cell state layer1
    float outb = ob[0];

    for (int t = 0; t < T_STEPS; t++) {
        // ---- compute ReLU GCN features for this t: intb[f][nl] ----
        const float* xat = xa + t * 2 * BN;
        for (int idx = tid; idx < 16 * BN; idx += NTHR) {
            int nl = idx & (BN - 1);
            int f  = idx >> 7;
            float v = fmaf(xat[nl], gws[f * 2],
                      fmaf(xat[BN + nl], gws[f * 2 + 1], gbs[f]));
            intb[idx] = fmaxf(v, 0.0f);
        }
        __syncthreads();

        ull acc[8][4];
#pragma unroll
        for (int c = 0; c < 8; c++)
#pragma unroll
            for (int p = 0; p < 4; p++) acc[c][p] = 0ull;

        // ---- layer0 GEMM: gates = in_t @ Wih0^T + h0 @ Whh0^T ----
#pragma unroll 2
        for (int k = 0; k < 16; k++)
            gemm_step2(wsd0 + k * 256, intb + k * 128, ubase2, nbase, acc);
#pragma unroll 2
        for (int k = 0; k < 32; k++)
            gemm_step2(wsd0 + (16 + k) * 256, h0b + k * 128, ubase2, nbase, acc);
        __syncthreads();    // all reads of h0b (and intb) done

        {
            float hA[8], hB[8];
            lstm_act2(acc, bias0, ucol, c0a, c0b, hA, hB);
            int u0 = up * 2;
            *(float4*)(h0b + u0 * 128 + nbase)           = make_float4(hA[0], hA[1], hA[2], hA[3]);
            *(float4*)(h0b + u0 * 128 + nbase + 4)       = make_float4(hA[4], hA[5], hA[6], hA[7]);
            *(float4*)(h0b + (u0 + 1) * 128 + nbase)     = make_float4(hB[0], hB[1], hB[2], hB[3]);
            *(float4*)(h0b + (u0 + 1) * 128 + nbase + 4) = make_float4(hB[4], hB[5], hB[6], hB[7]);
        }
        __syncthreads();    // new h0 visible

        // ---- layer1 GEMM: gates = h0 @ Wih1^T + h1 @ Whh1^T ----
#pragma unroll
        for (int c = 0; c < 8; c++)
#pragma unroll
            for (int p = 0; p < 4; p++) acc[c][p] = 0ull;
#pragma unroll 2
        for (int k = 0; k < 32; k++)
            gemm_step2(wsd1 + k * 256, h0b + k * 128, ubase2, nbase, acc);
#pragma unroll 2
        for (int k = 0; k < 32; k++)
            gemm_step2(wsd1 + (32 + k) * 256, h1b + k * 128, ubase2, nbase, acc);
        __syncthreads();    // all reads of h1b done

        {
            float hA[8], hB[8];
            lstm_act2(acc, bias1, ucol, c1a, c1b, hA, hB);
            int u0 = up * 2;
            *(float4*)(h1b + u0 * 128 + nbase)           = make_float4(hA[0], hA[1], hA[2], hA[3]);
            *(float4*)(h1b + u0 * 128 + nbase + 4)       = make_float4(hA[4], hA[5], hA[6], hA[7]);
            *(float4*)(h1b + (u0 + 1) * 128 + nbase)     = make_float4(hB[0], hB[1], hB[2], hB[3]);
            *(float4*)(h1b + (u0 + 1) * 128 + nbase + 4) = make_float4(hB[4], hB[5], hB[6], hB[7]);
        }
        __syncthreads();    // new h1 visible

        // ---- output projection out[t][n] = h1 . out_w + out_b ----
        if (tid < BN) {
            int n = node0 + tid;
            if (n < NN) {
                float s = outb;
#pragma unroll
                for (int u = 0; u < 32; u++) s = fmaf(h1b[u * 128 + tid], outw[u], s);
                out[t * NN + n] = s;
            }
        }
        // h1b/intb reads above complete before the next top-of-loop barrier
    }
}

// ---------------- launcher ----------------
extern "C" void kernel_launch(void* const* d_in, const int* in_sizes, int n_in,
                              void* d_out, int out_size) {
    const float* x    = (const float*)d_in[0];
    const int*   ei   = (const int*)  d_in[1];
    const float* gw   = (const float*)d_in[2];
    const float* gb   = (const float*)d_in[3];
    const float* wih0 = (const float*)d_in[4];
    const float* whh0 = (const float*)d_in[5];
    const float* bih0 = (const float*)d_in[6];
    const float* bhh0 = (const float*)d_in[7];
    const float* wih1 = (const float*)d_in[8];
    const float* whh1 = (const float*)d_in[9];
    const float* bih1 = (const float*)d_in[10];
    const float* bhh1 = (const float*)d_in[11];
    const float* ow   = (const float*)d_in[12];
    const float* ob   = (const float*)d_in[13];
    float* out = (float*)d_out;

    cudaFuncSetAttribute(k_main, cudaFuncAttributeMaxDynamicSharedMemorySize, SM_BYTES);

    k_init_deg<<<(NN + 255) / 256, 256>>>();
    k_count   <<<(NE + 255) / 256, 256>>>(ei);
    k_dinv    <<<(NN + 255) / 256, 256>>>();
    k_xs      <<<(T_STEPS * NN * F_INN + 255) / 256, 256>>>(x);
    k_scatter <<<(NE * 5 + 255) / 256, 256>>>(ei);
    k_main    <<<(NN + BN - 1) / BN, NTHR, SM_BYTES>>>(
        wih0, whh0, bih0, bhh0, wih1, whh1, bih1, bhh1, gw, gb, ow, ob, out);
}

// round 4
// speedup vs baseline: 2.8021x; 2.8021x over previous
#include <cuda_runtime.h>
#include <cuda_bf16.h>
#include <cstdint>

#define T_STEPS 10
#define NN      50000
#define NE      800000

#define BN      128
#define NTHR    256

#define S0      52      // A0 row stride in floats (48 cols + pad), 52 % 32 = 20 -> conflict-free
#define S1      68      // A1 row stride (64 cols + pad), 68 % 32 = 4  -> conflict-free

// ---------------- device scratch ----------------
__device__ float g_deg [NN];
__device__ float g_dinv[NN];
__device__ float g_xs  [NN * 20];
__device__ float g_acc [NN * 20];

// ---------------- prep kernels (unchanged from R2) ----------------
__global__ void k_init_deg() {
    int n = blockIdx.x * blockDim.x + threadIdx.x;
    if (n < NN) g_deg[n] = 1.0f;
}
__global__ void k_count(const int* __restrict__ ei) {
    int e = blockIdx.x * blockDim.x + threadIdx.x;
    if (e < NE) atomicAdd(&g_deg[ei[NE + e]], 1.0f);
}
__global__ void k_dinv() {
    int n = blockIdx.x * blockDim.x + threadIdx.x;
    if (n < NN) g_dinv[n] = rsqrtf(g_deg[n]);
}
__global__ void k_xs(const float* __restrict__ x) {
    int idx = blockIdx.x * blockDim.x + threadIdx.x;
    if (idx < T_STEPS * NN * 2) {
        int n = (idx >> 1) % NN;
        int t = idx / (NN * 2);
        int k = idx & 1;
        float v = g_dinv[n] * x[idx];
        int o = n * 20 + t * 2 + k;
        g_xs[o]  = v;
        g_acc[o] = v;
    }
}
__global__ void k_scatter(const int* __restrict__ ei) {
    int idx = blockIdx.x * blockDim.x + threadIdx.x;
    if (idx >= NE * 5) return;
    int e = idx / 5;
    int q = idx - e * 5;
    int s = ei[e];
    int d = ei[NE + e];
    float4 v = *(const float4*)&g_xs[s * 20 + q * 4];
    float* a = &g_acc[d * 20 + q * 4];
    atomicAdd(a + 0, v.x);
    atomicAdd(a + 1, v.y);
    atomicAdd(a + 2, v.z);
    atomicAdd(a + 3, v.w);
}

// ---------------- math helpers ----------------
__device__ __forceinline__ float tanhap(float x) {
    float y;
    asm("tanh.approx.f32 %0, %1;" : "=f"(y) : "f"(x));
    return y;
}
__device__ __forceinline__ float sigf(float x) {
    return fmaf(tanhap(0.5f * x), 0.5f, 0.5f);
}
__device__ __forceinline__ uint32_t tf32b(float x) {
    uint32_t y;
    asm("cvt.rna.tf32.f32 %0, %1;" : "=r"(y) : "f"(x));
    return y;
}
__device__ __forceinline__ void mma_tf32(float d[4], uint32_t a0, uint32_t a1,
                                         uint32_t a2, uint32_t a3,
                                         uint32_t b0, uint32_t b1) {
    asm volatile(
        "mma.sync.aligned.m16n8k8.row.col.f32.tf32.tf32.f32 "
        "{%0,%1,%2,%3}, {%4,%5,%6,%7}, {%8,%9}, {%0,%1,%2,%3};"
        : "+f"(d[0]), "+f"(d[1]), "+f"(d[2]), "+f"(d[3])
        : "r"(a0), "r"(a1), "r"(a2), "r"(a3), "r"(b0), "r"(b1));
}

// smem layout (floats)
#define O_WF0 0                          // [6 kk][16 j][32 lane][2] = 6144
#define O_WF1 (O_WF0 + 6 * 16 * 64)      // [8][16][32][2] = 8192 -> 14336
#define O_BS0 (O_WF1 + 8 * 16 * 64)      // 14336, [128]
#define O_BS1 (O_BS0 + 128)              // 14464
#define O_OW  (O_BS1 + 128)              // 14592, [32]
#define O_GW  (O_OW + 32)                // 14624, [32]
#define O_GB  (O_GW + 32)                // 14656, [16]
#define O_XA  (O_GB + 16)                // 14672, [10][2][128] = 2560
#define O_A0  (O_XA + T_STEPS * 2 * 128) // 17232, [128][S0] = 6656
#define O_A1  (O_A0 + 128 * S0)          // 23888, [128][S1] = 8704
#define SM_FLOATS (O_A1 + 128 * S1)      // 32592
#define SM_BYTES  (SM_FLOATS * 4)        // 130368

__global__ __launch_bounds__(NTHR, 1)
void k_main(const float* __restrict__ wih0, const float* __restrict__ whh0,
            const float* __restrict__ bih0, const float* __restrict__ bhh0,
            const float* __restrict__ wih1, const float* __restrict__ whh1,
            const float* __restrict__ bih1, const float* __restrict__ bhh1,
            const float* __restrict__ gw,   const float* __restrict__ gb,
            const float* __restrict__ ow,   const float* __restrict__ ob,
            float* __restrict__ out) {
    extern __shared__ float sm[];
    uint32_t* wf0 = (uint32_t*)(sm + O_WF0);
    uint32_t* wf1 = (uint32_t*)(sm + O_WF1);
    float* bs0 = sm + O_BS0;
    float* bs1 = sm + O_BS1;
    float* ows = sm + O_OW;
    float* gws = sm + O_GW;
    float* gbs = sm + O_GB;
    float* xa  = sm + O_XA;
    uint32_t* A0 = (uint32_t*)(sm + O_A0);
    uint32_t* A1 = (uint32_t*)(sm + O_A1);

    int tid = threadIdx.x;
    int node0 = blockIdx.x * BN;

    // ---- prologue: weights in B-fragment order (tf32) ----
    // idx -> kk, j, lane, half ; element = Wt[kk*8 + (lane&3) + half*4][j*8 + (lane>>2)]
    for (int idx = tid; idx < 6 * 16 * 64; idx += NTHR) {
        int kk = idx >> 10;
        int rem = idx & 1023;
        int j = rem >> 6;
        int ll = (rem >> 1) & 31;
        int half = rem & 1;
        int k = kk * 8 + (ll & 3) + half * 4;
        int c = j * 8 + (ll >> 2);                 // torch row (gate col)
        float v = (k < 16) ? wih0[c * 16 + k] : whh0[c * 32 + (k - 16)];
        wf0[idx] = tf32b(v);
    }
    for (int idx = tid; idx < 8 * 16 * 64; idx += NTHR) {
        int kk = idx >> 10;
        int rem = idx & 1023;
        int j = rem >> 6;
        int ll = (rem >> 1) & 31;
        int half = rem & 1;
        int k = kk * 8 + (ll & 3) + half * 4;
        int c = j * 8 + (ll >> 2);
        float v = (k < 32) ? wih1[c * 32 + k] : whh1[c * 32 + (k - 32)];
        wf1[idx] = tf32b(v);
    }
    if (tid < 128) { bs0[tid] = bih0[tid] + bhh0[tid]; bs1[tid] = bih1[tid] + bhh1[tid]; }
    if (tid < 32) { ows[tid] = ow[tid]; gws[tid] = gw[tid]; }
    if (tid < 16) gbs[tid] = gb[tid];
    for (int idx = tid; idx < 128 * S0; idx += NTHR) A0[idx] = 0u;
    for (int idx = tid; idx < 128 * S1; idx += NTHR) A1[idx] = 0u;

    // ---- per-tile aggregated raw features ----
    for (int idx = tid; idx < T_STEPS * 2 * BN; idx += NTHR) {
        int nl = idx & (BN - 1);
        int rest = idx >> 7;
        int n = node0 + nl;
        if (n >= NN) n = NN - 1;
        xa[idx] = g_acc[n * 20 + rest] * g_dinv[n];
    }
    __syncthreads();

    // ---- warp/lane geometry ----
    int w = tid >> 5;
    int l = tid & 31;
    int r0 = w * 16 + (l >> 2);      // local node row (and r0+8)
    int cb = 2 * (l & 3);            // col pair base within 8-wide tile

    float c0[16], c1[16];
#pragma unroll
    for (int i = 0; i < 16; i++) { c0[i] = 0.0f; c1[i] = 0.0f; }
    float obv = ob[0];

    for (int t = 0; t < T_STEPS; t++) {
        // ---- write GCN ReLU features (tf32) into A0 cols 0..15 ----
        {
            int nl = tid >> 1;
            int f0 = (tid & 1) * 8;
            float x0v = xa[t * 256 + nl];
            float x1v = xa[t * 256 + 128 + nl];
            uint32_t fv[8];
#pragma unroll
            for (int f = 0; f < 8; f++) {
                float v = fmaf(x0v, gws[(f0 + f) * 2],
                          fmaf(x1v, gws[(f0 + f) * 2 + 1], gbs[f0 + f]));
                fv[f] = tf32b(fmaxf(v, 0.0f));
            }
            uint32_t* p = A0 + nl * S0 + f0;
            *(uint4*)(p)     = make_uint4(fv[0], fv[1], fv[2], fv[3]);
            *(uint4*)(p + 4) = make_uint4(fv[4], fv[5], fv[6], fv[7]);
        }
        __syncthreads();   // B1: feats + h1(t-1) visible

        // ---- layer0 GEMM: [16 nodes] x [128 gates] x K=48 ----
        float d[16][4];
#pragma unroll
        for (int j = 0; j < 16; j++) {
            float b0v = bs0[j * 8 + cb], b1v = bs0[j * 8 + cb + 1];
            d[j][0] = b0v; d[j][1] = b1v; d[j][2] = b0v; d[j][3] = b1v;
        }
#pragma unroll
        for (int kk = 0; kk < 6; kk++) {
            int ab = r0 * S0 + kk * 8 + (l & 3);
            uint32_t a0 = A0[ab], a1 = A0[ab + 8 * S0];
            uint32_t a2 = A0[ab + 4], a3 = A0[ab + 8 * S0 + 4];
            const uint2* bp = (const uint2*)wf0 + kk * 16 * 32 + l;
#pragma unroll
            for (int j = 0; j < 16; j++) {
                uint2 b = bp[j * 32];
                mma_tf32(d[j], a0, a1, a2, a3, b.x, b.y);
            }
        }
        __syncthreads();   // B2: all warps done reading A0 (h0 prev)

        // ---- layer0 activations; h0 -> A0[16..47] and A1[0..31] ----
#pragma unroll
        for (int m = 0; m < 4; m++)
#pragma unroll
            for (int rho = 0; rho < 2; rho++)
#pragma unroll
                for (int p = 0; p < 2; p++) {
                    int q = 2 * rho + p;
                    int ci = (m * 2 + rho) * 2 + p;
                    float gi = d[0 * 4 + m][q], gf = d[1 * 4 + m][q];
                    float gg = d[2 * 4 + m][q], go = d[3 * 4 + m][q];
                    float cc = sigf(gf) * c0[ci] + sigf(gi) * tanhap(gg);
                    c0[ci] = cc;
                    float h = sigf(go) * tanhap(cc);
                    int u = 8 * m + cb + p;
                    int node = r0 + 8 * rho;
                    uint32_t hb = tf32b(h);
                    A0[node * S0 + 16 + u] = hb;
                    A1[node * S1 + u]      = hb;
                }
        __syncthreads();   // B3: new h0 visible

        // ---- layer1 GEMM: K=64 (h0 new | h1 prev) ----
#pragma unroll
        for (int j = 0; j < 16; j++) {
            float b0v = bs1[j * 8 + cb], b1v = bs1[j * 8 + cb + 1];
            d[j][0] = b0v; d[j][1] = b1v; d[j][2] = b0v; d[j][3] = b1v;
        }
#pragma unroll
        for (int kk = 0; kk < 8; kk++) {
            int ab = r0 * S1 + kk * 8 + (l & 3);
            uint32_t a0 = A1[ab], a1 = A1[ab + 8 * S1];
            uint32_t a2 = A1[ab + 4], a3 = A1[ab + 8 * S1 + 4];
            const uint2* bp = (const uint2*)wf1 + kk * 16 * 32 + l;
#pragma unroll
            for (int j = 0; j < 16; j++) {
                uint2 b = bp[j * 32];
                mma_tf32(d[j], a0, a1, a2, a3, b.x, b.y);
            }
        }
        __syncthreads();   // B4: all warps done reading A1 (h1 prev)

        // ---- layer1 activations; h1 -> A1[32..63]; fused output proj ----
        float po0 = 0.0f, po1 = 0.0f;
#pragma unroll
        for (int m = 0; m < 4; m++)
#pragma unroll
            for (int rho = 0; rho < 2; rho++)
#pragma unroll
                for (int p = 0; p < 2; p++) {
                    int q = 2 * rho + p;
                    int ci = (m * 2 + rho) * 2 + p;
                    float gi = d[0 * 4 + m][q], gf = d[1 * 4 + m][q];
                    float gg = d[2 * 4 + m][q], go = d[3 * 4 + m][q];
                    float cc = sigf(gf) * c1[ci] + sigf(gi) * tanhap(gg);
                    c1[ci] = cc;
                    float h = sigf(go) * tanhap(cc);
                    int u = 8 * m + cb + p;
                    int node = r0 + 8 * rho;
                    A1[node * S1 + 32 + u] = tf32b(h);
                    float hw = h * ows[u];
                    if (rho == 0) po0 += hw; else po1 += hw;
                }
        // reduce across the 4 lanes sharing the same node rows
        po0 += __shfl_xor_sync(0xFFFFFFFFu, po0, 1);
        po0 += __shfl_xor_sync(0xFFFFFFFFu, po0, 2);
        po1 += __shfl_xor_sync(0xFFFFFFFFu, po1, 1);
        po1 += __shfl_xor_sync(0xFFFFFFFFu, po1, 2);
        if ((l & 3) == 0) {
            int n0 = node0 + r0;
            if (n0 < NN)     out[t * NN + n0]     = po0 + obv;
            int n1 = node0 + r0 + 8;
            if (n1 < NN)     out[t * NN + n1]     = po1 + obv;
        }
        // next iteration's B1 orders the h1 stores before their readers
    }
}

// ---------------- launcher ----------------
extern "C" void kernel_launch(void* const* d_in, const int* in_sizes, int n_in,
                              void* d_out, int out_size) {
    const float* x    = (const float*)d_in[0];
    const int*   ei   = (const int*)  d_in[1];
    const float* gw   = (const float*)d_in[2];
    const float* gb   = (const float*)d_in[3];
    const float* wih0 = (const float*)d_in[4];
    const float* whh0 = (const float*)d_in[5];
    const float* bih0 = (const float*)d_in[6];
    const float* bhh0 = (const float*)d_in[7];
    const float* wih1 = (const float*)d_in[8];
    const float* whh1 = (const float*)d_in[9];
    const float* bih1 = (const float*)d_in[10];
    const float* bhh1 = (const float*)d_in[11];
    const float* ow   = (const float*)d_in[12];
    const float* ob   = (const float*)d_in[13];
    float* out = (float*)d_out;

    cudaFuncSetAttribute(k_main, cudaFuncAttributeMaxDynamicSharedMemorySize, SM_BYTES);

    k_init_deg<<<(NN + 255) / 256, 256>>>();
    k_count   <<<(NE + 255) / 256, 256>>>(ei);
    k_dinv    <<<(NN + 255) / 256, 256>>>();
    k_xs      <<<(T_STEPS * NN * 2 + 255) / 256, 256>>>(x);
    k_scatter <<<(NE * 5 + 255) / 256, 256>>>(ei);
    k_main    <<<(NN + BN - 1) / BN, NTHR, SM_BYTES>>>(
        wih0, whh0, bih0, bhh0, wih1, whh1, bih1, bhh1, gw, gb, ow, ob, out);
}